// round 2
// baseline (speedup 1.0000x reference)
#include <cuda_runtime.h>

// LoRA linear, factored through rank-16:
//   t   = x @ A^T   : [16384,4096] @ [4096,16] -> [16384,16]
//   out = t @ B^T   : [16384,16]   @ [16,4096] -> [16384,4096]

#define D 4096
#define R 16
#define ROWS_TOTAL 16384
#define KC 512
#define AS_STRIDE 516   // 512 + 4 floats pad

typedef unsigned long long u64;

__device__ float g_t[ROWS_TOTAL * R];   // 1 MB scratch, L2-resident

// packed 2xfp32 FMA (Blackwell f32x2: 2x scalar FFMA throughput, PTX-only)
__device__ __forceinline__ u64 fma2(u64 a, u64 b, u64 c) {
    u64 d;
    asm("fma.rn.f32x2 %0, %1, %2, %3;" : "=l"(d) : "l"(a), "l"(b), "l"(c));
    return d;
}
__device__ __forceinline__ float hsum2(u64 v) {
    float lo, hi;
    asm("mov.b64 {%0, %1}, %2;" : "=f"(lo), "=f"(hi) : "l"(v));
    return lo + hi;
}

// ---------------- Stage 1: t = x @ A^T ----------------
// Block: 256 thr (8 warps), 4 rows/warp -> 32 rows/block, grid 512.
// Lane split: rq = lane>>3 owns r-quarter (4 r), k8 = lane&7 splits k 8-way.
// Accumulators: 4 rows x 4 r in f32x2 over (k,k+1) pairs = 16 u64.
__global__ void __launch_bounds__(256, 3)
lora_stage1(const float* __restrict__ x, const float* __restrict__ A)
{
    __shared__ float as[R * AS_STRIDE];   // ~33 KB A chunk [16][512]

    const int tid  = threadIdx.x;
    const int w    = tid >> 5;
    const int lane = tid & 31;
    const int rq   = lane >> 3;
    const int k8   = lane & 7;
    const long row0 = (long)blockIdx.x * 32 + w * 4;

    u64 acc[4][4];
    #pragma unroll
    for (int i = 0; i < 4; ++i)
        #pragma unroll
        for (int j = 0; j < 4; ++j) acc[i][j] = 0ULL;

    for (int c = 0; c < D / KC; ++c) {
        __syncthreads();
        // cooperative load A chunk [16][512] into padded smem
        #pragma unroll
        for (int t4 = 0; t4 < (R * KC / 4) / 256; ++t4) {
            int idx = tid + t4 * 256;
            int r   = idx >> 7;     // / (KC/4 = 128)
            int kf  = idx & 127;
            *(float4*)(as + r * AS_STRIDE + kf * 4) =
                *(const float4*)(A + (long)r * D + c * KC + kf * 4);
        }
        __syncthreads();

        #pragma unroll
        for (int s = 0; s < KC / 32; ++s) {
            const int ks = s * 32 + k8 * 4;
            const int kg = c * KC + ks;
            ulonglong2 xv[4];
            #pragma unroll
            for (int i = 0; i < 4; ++i)
                xv[i] = *(const ulonglong2*)(x + (row0 + i) * D + kg);
            #pragma unroll
            for (int j = 0; j < 4; ++j) {
                ulonglong2 av = *(const ulonglong2*)(as + (rq * 4 + j) * AS_STRIDE + ks);
                #pragma unroll
                for (int i = 0; i < 4; ++i) {
                    acc[i][j] = fma2(xv[i].x, av.x, acc[i][j]);
                    acc[i][j] = fma2(xv[i].y, av.y, acc[i][j]);
                }
            }
        }
    }

    // reduce f32x2 halves + butterfly across the 8 k-split lanes (bits 0..2)
    float s[4][4];
    #pragma unroll
    for (int i = 0; i < 4; ++i)
        #pragma unroll
        for (int j = 0; j < 4; ++j) {
            float v = hsum2(acc[i][j]);
            v += __shfl_xor_sync(0xffffffffu, v, 4);
            v += __shfl_xor_sync(0xffffffffu, v, 2);
            v += __shfl_xor_sync(0xffffffffu, v, 1);
            s[i][j] = v;
        }
    if (k8 == 0) {
        #pragma unroll
        for (int i = 0; i < 4; ++i)
            *(float4*)(g_t + (row0 + i) * R + rq * 4) =
                make_float4(s[i][0], s[i][1], s[i][2], s[i][3]);
    }
}

// ---------------- Stage 2: out = t @ B^T ----------------
// Block: 256 thr, tile 64 rows x 1024 cols. Thread owns 4 consecutive cols;
// its B[4][16] sub-block lives in registers (reused over 64 rows).
// t tile in smem, broadcast reads. STG.128 coalesced stores.
__global__ void __launch_bounds__(256, 2)
lora_stage2(const float* __restrict__ B, float* __restrict__ out)
{
    __shared__ float ts[64 * R];   // 4 KB

    const int tid = threadIdx.x;
    const long rowBase = (long)blockIdx.y * 64;
    const int ob = blockIdx.x * 1024 + tid * 4;

    // load t tile: 64*16 = 1024 floats = 256 float4
    *(float4*)(ts + tid * 4) = *(const float4*)(g_t + rowBase * R + tid * 4);

    // load B sub-block into regs
    u64 bb[4][8];
    #pragma unroll
    for (int j = 0; j < 4; ++j) {
        const float* bp = B + (long)(ob + j) * R;
        ulonglong2 v0 = *(const ulonglong2*)(bp);
        ulonglong2 v1 = *(const ulonglong2*)(bp + 4);
        ulonglong2 v2 = *(const ulonglong2*)(bp + 8);
        ulonglong2 v3 = *(const ulonglong2*)(bp + 12);
        bb[j][0] = v0.x; bb[j][1] = v0.y;
        bb[j][2] = v1.x; bb[j][3] = v1.y;
        bb[j][4] = v2.x; bb[j][5] = v2.y;
        bb[j][6] = v3.x; bb[j][7] = v3.y;
    }
    __syncthreads();

    for (int row = 0; row < 64; ++row) {
        u64 tt[8];
        #pragma unroll
        for (int q = 0; q < 4; ++q) {
            ulonglong2 v = *(const ulonglong2*)(ts + row * R + q * 4);
            tt[2 * q]     = v.x;
            tt[2 * q + 1] = v.y;
        }
        float res[4];
        #pragma unroll
        for (int j = 0; j < 4; ++j) {
            u64 a = 0ULL;
            #pragma unroll
            for (int p = 0; p < 8; ++p)
                a = fma2(bb[j][p], tt[p], a);
            res[j] = hsum2(a);
        }
        *(float4*)(out + (rowBase + row) * (long)D + ob) =
            make_float4(res[0], res[1], res[2], res[3]);
    }
}

extern "C" void kernel_launch(void* const* d_in, const int* in_sizes, int n_in,
                              void* d_out, int out_size) {
    const float* x = (const float*)d_in[0];   // [16384, 4096]
    const float* A = (const float*)d_in[1];   // [16, 4096]
    const float* B = (const float*)d_in[2];   // [4096, 16]
    float* out = (float*)d_out;               // [16384, 4096]

    lora_stage1<<<ROWS_TOTAL / 32, 256>>>(x, A);
    dim3 g2(D / 1024, ROWS_TOTAL / 64);
    lora_stage2<<<g2, 256>>>(B, out);
}

// round 3
// speedup vs baseline: 1.3930x; 1.3930x over previous
#include <cuda_runtime.h>
#include <cstdint>

// LoRA linear via rank-16 factor:
//   t   = x @ A^T   : [16384,4096] @ [4096,16] -> [16384,16]   (stage 1)
//   out = t @ B^T   : [16384,16]   @ [16,4096] -> [16384,4096] (stage 2)

#define D 4096
#define R 16
#define ROWS_TOTAL 16384
#define KC 128
#define AST 18          // transposed A smem stride (conflict-free LDS.64)

typedef unsigned long long u64;

__device__ float g_t[ROWS_TOTAL * R];   // 1 MB scratch (fully overwritten, L2-resident)

__device__ __forceinline__ u64 fma2(u64 a, u64 b, u64 c) {
    u64 d; asm("fma.rn.f32x2 %0,%1,%2,%3;" : "=l"(d) : "l"(a), "l"(b), "l"(c)); return d;
}
__device__ __forceinline__ u64 add2(u64 a, u64 b) {
    u64 d; asm("add.rn.f32x2 %0,%1,%2;" : "=l"(d) : "l"(a), "l"(b)); return d;
}
__device__ __forceinline__ u64 pack2(float s) {
    u64 d; asm("mov.b64 %0,{%1,%1};" : "=l"(d) : "f"(s)); return d;
}
__device__ __forceinline__ float hsum2(u64 v) {
    float lo, hi; asm("mov.b64 {%0,%1},%2;" : "=f"(lo), "=f"(hi) : "l"(v)); return lo + hi;
}
__device__ __forceinline__ void cp16(uint32_t d, const void* s) {
    asm volatile("cp.async.cg.shared.global [%0],[%1],16;" :: "r"(d), "l"(s));
}
__device__ __forceinline__ void cpcommit() { asm volatile("cp.async.commit_group;"); }
__device__ __forceinline__ void cpwait0()  { asm volatile("cp.async.wait_group 0;"); }

// ---------------- Stage 1: t = x @ A^T ----------------
// Block 256 thr / 8 warps, tile 32 rows. Warp (g = w>>1, h = w&1):
// rows g*8..g*8+7, r-half h*8..h*8+7. Lane splits k 32-way.
// acc[8 rows][4 r-pairs] packed f32x2 over (r, r+1).
// x tiles double-buffered via cp.async; A chunk transposed in smem [k][r].
__global__ void __launch_bounds__(256, 2)
lora_stage1(const float* __restrict__ x, const float* __restrict__ A)
{
    __shared__ float xs[2 * 32 * KC];   // 32 KB
    __shared__ float ast[KC * AST];     // 9 KB (single buffer, reg-staged swap)

    const int tid = threadIdx.x;
    const int w = tid >> 5, lane = tid & 31;
    const int g = w >> 1, h = w & 1;
    const long rowBase = (long)blockIdx.x * 32;

    // copy roles
    const int crow = tid >> 3, cseg = tid & 7;   // x: row, 16-float segment
    const int ar = tid & 15, akg = tid >> 4;     // A: r, k-group of 8

    const float* xsrc = x + (rowBase + crow) * D + cseg * 16;
    const float* asrc = A + (long)ar * D + akg * 8;
    const uint32_t xs_base = (uint32_t)__cvta_generic_to_shared(xs);

    u64 acc[8][4];
    #pragma unroll
    for (int i = 0; i < 8; ++i)
        #pragma unroll
        for (int j = 0; j < 4; ++j) acc[i][j] = 0ULL;

    // ---- prologue: chunk 0 in flight ----
    {
        uint32_t dst = xs_base + (uint32_t)(crow * KC + cseg * 16) * 4u;
        cp16(dst,      xsrc);
        cp16(dst + 16, xsrc + 4);
        cp16(dst + 32, xsrc + 8);
        cp16(dst + 48, xsrc + 12);
        cpcommit();
        float4 a0 = *(const float4*)asrc;
        float4 a1 = *(const float4*)(asrc + 4);
        ast[(akg * 8 + 0) * AST + ar] = a0.x;
        ast[(akg * 8 + 1) * AST + ar] = a0.y;
        ast[(akg * 8 + 2) * AST + ar] = a0.z;
        ast[(akg * 8 + 3) * AST + ar] = a0.w;
        ast[(akg * 8 + 4) * AST + ar] = a1.x;
        ast[(akg * 8 + 5) * AST + ar] = a1.y;
        ast[(akg * 8 + 6) * AST + ar] = a1.z;
        ast[(akg * 8 + 7) * AST + ar] = a1.w;
    }

    for (int c = 0; c < D / KC; ++c) {
        const int buf = c & 1;
        cpwait0();
        __syncthreads();   // xs[buf] + ast (chunk c) visible to all

        float4 a0, a1;
        if (c < 31) {
            // prefetch next x tile into xs[buf^1], next A chunk into regs
            const float* xsn = xsrc + (c + 1) * KC;
            uint32_t dst = xs_base +
                (uint32_t)(((buf ^ 1) * 32 * KC) + crow * KC + cseg * 16) * 4u;
            cp16(dst,      xsn);
            cp16(dst + 16, xsn + 4);
            cp16(dst + 32, xsn + 8);
            cp16(dst + 48, xsn + 12);
            cpcommit();
            const float* an = asrc + (c + 1) * KC;
            a0 = *(const float4*)an;
            a1 = *(const float4*)(an + 4);
        }

        // ---- compute chunk c (fully smem-fed) ----
        const float* xp = xs + buf * 32 * KC + g * 8 * KC;
        #pragma unroll
        for (int st = 0; st < 4; ++st) {
            const int k = st * 32 + lane;
            const float* ak = ast + k * AST + h * 8;
            u64 av0 = *(const u64*)(ak);
            u64 av1 = *(const u64*)(ak + 2);
            u64 av2 = *(const u64*)(ak + 4);
            u64 av3 = *(const u64*)(ak + 6);
            #pragma unroll
            for (int ih = 0; ih < 2; ++ih) {
                u64 xv0 = pack2(xp[(ih * 4 + 0) * KC + k]);
                u64 xv1 = pack2(xp[(ih * 4 + 1) * KC + k]);
                u64 xv2 = pack2(xp[(ih * 4 + 2) * KC + k]);
                u64 xv3 = pack2(xp[(ih * 4 + 3) * KC + k]);
                acc[ih*4+0][0] = fma2(xv0, av0, acc[ih*4+0][0]);
                acc[ih*4+0][1] = fma2(xv0, av1, acc[ih*4+0][1]);
                acc[ih*4+0][2] = fma2(xv0, av2, acc[ih*4+0][2]);
                acc[ih*4+0][3] = fma2(xv0, av3, acc[ih*4+0][3]);
                acc[ih*4+1][0] = fma2(xv1, av0, acc[ih*4+1][0]);
                acc[ih*4+1][1] = fma2(xv1, av1, acc[ih*4+1][1]);
                acc[ih*4+1][2] = fma2(xv1, av2, acc[ih*4+1][2]);
                acc[ih*4+1][3] = fma2(xv1, av3, acc[ih*4+1][3]);
                acc[ih*4+2][0] = fma2(xv2, av0, acc[ih*4+2][0]);
                acc[ih*4+2][1] = fma2(xv2, av1, acc[ih*4+2][1]);
                acc[ih*4+2][2] = fma2(xv2, av2, acc[ih*4+2][2]);
                acc[ih*4+2][3] = fma2(xv2, av3, acc[ih*4+2][3]);
                acc[ih*4+3][0] = fma2(xv3, av0, acc[ih*4+3][0]);
                acc[ih*4+3][1] = fma2(xv3, av1, acc[ih*4+3][1]);
                acc[ih*4+3][2] = fma2(xv3, av2, acc[ih*4+3][2]);
                acc[ih*4+3][3] = fma2(xv3, av3, acc[ih*4+3][3]);
            }
        }

        __syncthreads();   // everyone done reading ast before overwrite
        if (c < 31) {
            ast[(akg * 8 + 0) * AST + ar] = a0.x;
            ast[(akg * 8 + 1) * AST + ar] = a0.y;
            ast[(akg * 8 + 2) * AST + ar] = a0.z;
            ast[(akg * 8 + 3) * AST + ar] = a0.w;
            ast[(akg * 8 + 4) * AST + ar] = a1.x;
            ast[(akg * 8 + 5) * AST + ar] = a1.y;
            ast[(akg * 8 + 6) * AST + ar] = a1.z;
            ast[(akg * 8 + 7) * AST + ar] = a1.w;
        }
    }

    // ---- butterfly all-reduce over the 32 k-split lanes (packed adds) ----
    #pragma unroll
    for (int i = 0; i < 8; ++i)
        #pragma unroll
        for (int j = 0; j < 4; ++j) {
            u64 v = acc[i][j];
            v = add2(v, __shfl_xor_sync(0xffffffffu, v, 16));
            v = add2(v, __shfl_xor_sync(0xffffffffu, v, 8));
            v = add2(v, __shfl_xor_sync(0xffffffffu, v, 4));
            v = add2(v, __shfl_xor_sync(0xffffffffu, v, 2));
            v = add2(v, __shfl_xor_sync(0xffffffffu, v, 1));
            acc[i][j] = v;
        }
    if (lane == 0) {
        #pragma unroll
        for (int i = 0; i < 8; ++i)
            #pragma unroll
            for (int j = 0; j < 4; ++j)
                *(u64*)(g_t + (rowBase + g * 8 + i) * R + h * 8 + 2 * j) = acc[i][j];
    }
}

// ---------------- Stage 2: out = t @ B^T ----------------
// Block 256 thr, tile 128 rows x 1024 cols. Thread owns 4 consecutive cols;
// B[4][16] sub-block in regs (reused over 128 rows). t tile broadcast from smem.
__global__ void __launch_bounds__(256, 2)
lora_stage2(const float* __restrict__ B, float* __restrict__ out)
{
    __shared__ float ts[128 * R];   // 8 KB

    const int tid = threadIdx.x;
    const long rowBase = (long)blockIdx.y * 128;
    const int ob = blockIdx.x * 1024 + tid * 4;

    *(float4*)(ts + tid * 8)     = *(const float4*)(g_t + rowBase * R + tid * 8);
    *(float4*)(ts + tid * 8 + 4) = *(const float4*)(g_t + rowBase * R + tid * 8 + 4);

    u64 bb[4][8];
    #pragma unroll
    for (int j = 0; j < 4; ++j) {
        const float* bp = B + (long)(ob + j) * R;
        ulonglong2 v0 = *(const ulonglong2*)(bp);
        ulonglong2 v1 = *(const ulonglong2*)(bp + 4);
        ulonglong2 v2 = *(const ulonglong2*)(bp + 8);
        ulonglong2 v3 = *(const ulonglong2*)(bp + 12);
        bb[j][0] = v0.x; bb[j][1] = v0.y;
        bb[j][2] = v1.x; bb[j][3] = v1.y;
        bb[j][4] = v2.x; bb[j][5] = v2.y;
        bb[j][6] = v3.x; bb[j][7] = v3.y;
    }
    __syncthreads();

    for (int row = 0; row < 128; ++row) {
        u64 tt[8];
        #pragma unroll
        for (int q = 0; q < 4; ++q) {
            ulonglong2 v = *(const ulonglong2*)(ts + row * R + q * 4);
            tt[2 * q]     = v.x;
            tt[2 * q + 1] = v.y;
        }
        float res[4];
        #pragma unroll
        for (int j = 0; j < 4; ++j) {
            u64 a = 0ULL;
            #pragma unroll
            for (int p = 0; p < 8; ++p)
                a = fma2(bb[j][p], tt[p], a);
            res[j] = hsum2(a);
        }
        *(float4*)(out + (rowBase + row) * (long)D + ob) =
            make_float4(res[0], res[1], res[2], res[3]);
    }
}

extern "C" void kernel_launch(void* const* d_in, const int* in_sizes, int n_in,
                              void* d_out, int out_size) {
    const float* x = (const float*)d_in[0];   // [16384, 4096]
    const float* A = (const float*)d_in[1];   // [16, 4096]
    const float* B = (const float*)d_in[2];   // [4096, 16]
    float* out = (float*)d_out;               // [16384, 4096]

    lora_stage1<<<ROWS_TOTAL / 32, 256>>>(x, A);
    dim3 g2(D / 1024, ROWS_TOTAL / 128);
    lora_stage2<<<g2, 256>>>(B, out);
}